// round 12
// baseline (speedup 1.0000x reference)
#include <cuda_runtime.h>
#include <cstdint>

// Degenerate conv (reference uses only x[:,0] and w[:,2]):
//   out(n,f,i,j) = bias[f] + sum_{a,b} w[f,2,a,b] * x[n,0,i+a,j+b]
//   x: (16,3,256,256) f32, w: (64,3,3,3) f32, b: (64,) f32
//   out: (16,64,254,254) f32
//
// 1 row x 4 cols per thread, 16 filters (blockIdx.z quarter), all main
// stores STG.128 (16B-aligned, warp-dense 512B/warp-instruction).
// Row stride 1016B == 8 mod 16, so even rows tile at j = 4t and odd rows
// at j = 4t + 2 (staggered) to keep 16B store alignment on every row.
// Lane t=63 of each row half covers the leftover 2-col strip (STG.64).
// Block 128 = 2 row-halves x 64 lanes; row parity = tid>>6 (warp-uniform).
// Weights in __constant__ (uniform LDC port); bias scalar uniform __ldg.
#define NB     16
#define F_OUT  64
#define F_Q    16
#define Hh     256
#define Ww     256
#define HO     254
#define WO     254
#define OIMG   (HO * WO)          // 64516

typedef unsigned long long u64;

__constant__ float c_w[F_OUT * 27];   // full weight tensor (we use [f][2][*])

// packed f32x2 FMA (Blackwell): d = a * w + c on both lanes
static __device__ __forceinline__ u64 ffma2(u64 a, u64 w, u64 c) {
    u64 d;
    asm("fma.rn.f32x2 %0, %1, %2, %3;" : "=l"(d) : "l"(a), "l"(w), "l"(c));
    return d;
}

static __device__ __forceinline__ u64 pack2(float lo, float hi) {
    u64 d;
    asm("mov.b64 %0, {%1, %2};" : "=l"(d) : "f"(lo), "f"(hi));
    return d;
}

__global__ __launch_bounds__(128) void conv2dcq_kernel(
    const float* __restrict__ x,
    const float* __restrict__ bias,
    float* __restrict__ out) {

    const int tid = threadIdx.x;
    const int rs  = tid >> 6;             // row parity within pair, warp-uniform
    const int t   = tid & 63;             // col tile 0..63
    const int i   = blockIdx.x * 2 + rs;  // output row 0..253
    const int n   = blockIdx.y;
    const int f0  = blockIdx.z * F_Q;     // block-uniform filter base

    const float* xrow = x + (size_t)n * 3 * Hh * Ww + (size_t)i * Ww;
    float* orow = out + (size_t)n * F_OUT * OIMG
                      + (size_t)f0 * OIMG
                      + (size_t)i * WO;

    if (t < 63) {
        // ---- main: 4 output cols at j = 4t + 2*rs (16B-aligned store) ----
        const int j = 4 * t + 2 * rs;

        // Pack pairs directly from load vectors (no raw staging buffer).
        // P[r][s] = (x[i+r][j+s], x[i+r][j+s+1]), r=0..2, s=0..4
        u64 P[3][5];
        if (rs == 0) {                    // warp-uniform branch, j % 4 == 0
            #pragma unroll
            for (int r = 0; r < 3; r++) {
                const float* xr = xrow + (size_t)r * Ww + j;
                const float4 a = *reinterpret_cast<const float4*>(xr);
                const float2 b = *reinterpret_cast<const float2*>(xr + 4);
                P[r][0] = pack2(a.x, a.y);
                P[r][1] = pack2(a.y, a.z);
                P[r][2] = pack2(a.z, a.w);
                P[r][3] = pack2(a.w, b.x);
                P[r][4] = pack2(b.x, b.y);
            }
        } else {                          // j % 4 == 2
            #pragma unroll
            for (int r = 0; r < 3; r++) {
                const float* xr = xrow + (size_t)r * Ww + j;
                const float2 a = *reinterpret_cast<const float2*>(xr);
                const float4 b = *reinterpret_cast<const float4*>(xr + 2);
                P[r][0] = pack2(a.x, a.y);
                P[r][1] = pack2(a.y, b.x);
                P[r][2] = pack2(b.x, b.y);
                P[r][3] = pack2(b.y, b.z);
                P[r][4] = pack2(b.z, b.w);
            }
        }

        float* ob = orow + j;

        #pragma unroll 4
        for (int f = f0; f < f0 + F_Q; f++) {
            const float* wf = c_w + f * 27 + 18;   // w[f,2,:,:], uniform LDC
            const float bv = __ldg(bias + f);      // uniform scalar, L1-hit
            u64 a0 = pack2(bv, bv);     // cols j, j+1
            u64 a1 = a0;                // cols j+2, j+3

            #pragma unroll
            for (int a = 0; a < 3; a++) {
                #pragma unroll
                for (int b = 0; b < 3; b++) {
                    const float ws = wf[a * 3 + b];   // constant port
                    const u64 wp = pack2(ws, ws);
                    a0 = ffma2(P[a][b],     wp, a0);
                    a1 = ffma2(P[a][b + 2], wp, a1);
                }
            }

            // 16B-aligned by construction: (1016*i + 4*j) % 16 == 0
            *reinterpret_cast<ulonglong2*>(ob) = make_ulonglong2(a0, a1);
            ob += (size_t)OIMG;
        }
    } else {
        // ---- strip: 2 cols at j = 252 (even rows) / j = 0 (odd rows) ----
        const int j = rs ? 0 : 252;

        u64 P[3][3];
        #pragma unroll
        for (int r = 0; r < 3; r++) {
            // col 252: byte 1008 (16B-aligned); col 0 trivially aligned
            const float4 a = *reinterpret_cast<const float4*>(
                xrow + (size_t)r * Ww + j);
            P[r][0] = pack2(a.x, a.y);
            P[r][1] = pack2(a.y, a.z);
            P[r][2] = pack2(a.z, a.w);
        }

        float* ob = orow + j;

        #pragma unroll 4
        for (int f = f0; f < f0 + F_Q; f++) {
            const float* wf = c_w + f * 27 + 18;
            const float bv = __ldg(bias + f);
            u64 a0 = pack2(bv, bv);

            #pragma unroll
            for (int a = 0; a < 3; a++) {
                #pragma unroll
                for (int b = 0; b < 3; b++) {
                    const float ws = wf[a * 3 + b];
                    a0 = ffma2(P[a][b], pack2(ws, ws), a0);
                }
            }

            *reinterpret_cast<u64*>(ob) = a0;   // 8B-aligned
            ob += (size_t)OIMG;
        }
    }
}

extern "C" void kernel_launch(void* const* d_in, const int* in_sizes, int n_in,
                              void* d_out, int out_size) {
    const float* x    = (const float*)d_in[0];
    const float* w    = (const float*)d_in[1];
    const float* bias = (const float*)d_in[2];
    float* out        = (float*)d_out;

    // Single CE node: stage weights into constant memory (D2D, capturable).
    cudaMemcpyToSymbolAsync(c_w, w, F_OUT * 27 * sizeof(float), 0,
                            cudaMemcpyDeviceToDevice, 0);

    dim3 grid(HO / 2, NB, F_OUT / F_Q);   // (127, 16, 4)
    conv2dcq_kernel<<<grid, 128>>>(x, bias, out);
}

// round 14
// speedup vs baseline: 1.0290x; 1.0290x over previous
#include <cuda_runtime.h>
#include <cstdint>

// Degenerate conv (reference uses only x[:,0] and w[:,2]):
//   out(n,f,i,j) = bias[f] + sum_{a,b} w[f,2,a,b] * x[n,0,i+a,j+b]
//   x: (16,3,256,256) f32, w: (64,3,3,3) f32, b: (64,) f32
//   out: (16,64,254,254) f32
//
// Main blocks (blockIdx.x < 127): 1 row x 4 cols per thread (t = 0..62),
// 16 filters, every store a 16B-aligned warp-dense STG.128. Even rows tile
// at j=4t (cols 0..251), odd rows at j=4t+2 (cols 2..253); row stride
// 1016B == 8 mod 16 makes both aligned. Lanes with t==63 idle (guard!).
// Strip block (blockIdx.x == 127): ragged edges. For row-pair ip,
// out[2ip][252..253] and out[2ip+1][0..1] are CONTIGUOUS + 16B-aligned
// -> one STG.128 per filter covers both edges.
// Weights in __constant__ (uniform LDC port, one CE node); bias via
// uniform LDG.128 with static component selects.
#define NB     16
#define F_OUT  64
#define F_Q    16
#define Hh     256
#define Ww     256
#define HO     254
#define WO     254
#define OIMG   (HO * WO)          // 64516

typedef unsigned long long u64;

__constant__ float c_w[F_OUT * 27];   // full weight tensor (we use [f][2][*])

// packed f32x2 FMA (Blackwell): d = a * w + c on both lanes
static __device__ __forceinline__ u64 ffma2(u64 a, u64 w, u64 c) {
    u64 d;
    asm("fma.rn.f32x2 %0, %1, %2, %3;" : "=l"(d) : "l"(a), "l"(w), "l"(c));
    return d;
}

static __device__ __forceinline__ u64 pack2(float lo, float hi) {
    u64 d;
    asm("mov.b64 %0, {%1, %2};" : "=l"(d) : "f"(lo), "f"(hi));
    return d;
}

__global__ __launch_bounds__(128) void conv2dcq_kernel(
    const float* __restrict__ x,
    const float* __restrict__ bias,
    float* __restrict__ out) {

    const int tid = threadIdx.x;
    const int n   = blockIdx.y;
    const int f0  = blockIdx.z * F_Q;     // block-uniform filter base

    const float* xim = x + (size_t)n * 3 * Hh * Ww;        // channel 0
    float* oimg = out + (size_t)n * F_OUT * OIMG + (size_t)f0 * OIMG;

    // bias for this quarter: 4 uniform LDG.128 (64B-aligned)
    const float4* b4 = reinterpret_cast<const float4*>(bias + f0);

    if (blockIdx.x < 127) {
        // ================= main: STG.128 tiles, t = 0..62 only =============
        const int rs = tid >> 6;              // row parity, warp-uniform
        const int t  = tid & 63;              // col tile 0..63
        if (t >= 63) return;                  // <-- coverage guard (R13 bug)

        const int i  = blockIdx.x * 2 + rs;   // output row
        const int j  = 4 * t + 2 * rs;        // 16B-aligned store col

        const float* xrow = xim + (size_t)i * Ww;

        // P[r][s] = (x[i+r][j+s], x[i+r][j+s+1]), r=0..2, s=0..4
        u64 P[3][5];
        if (rs == 0) {                        // warp-uniform branch
            #pragma unroll
            for (int r = 0; r < 3; r++) {
                const float* xr = xrow + (size_t)r * Ww + j;
                const float4 a = *reinterpret_cast<const float4*>(xr);
                const float2 b = *reinterpret_cast<const float2*>(xr + 4);
                P[r][0] = pack2(a.x, a.y);
                P[r][1] = pack2(a.y, a.z);
                P[r][2] = pack2(a.z, a.w);
                P[r][3] = pack2(a.w, b.x);
                P[r][4] = pack2(b.x, b.y);
            }
        } else {
            #pragma unroll
            for (int r = 0; r < 3; r++) {
                const float* xr = xrow + (size_t)r * Ww + j;
                const float2 a = *reinterpret_cast<const float2*>(xr);
                const float4 b = *reinterpret_cast<const float4*>(xr + 2);
                P[r][0] = pack2(a.x, a.y);
                P[r][1] = pack2(a.y, b.x);
                P[r][2] = pack2(b.x, b.y);
                P[r][3] = pack2(b.y, b.z);
                P[r][4] = pack2(b.z, b.w);
            }
        }

        float* ob = oimg + (size_t)i * WO + j;

        #pragma unroll
        for (int g = 0; g < 4; g++) {
            const float4 bq = __ldg(b4 + g);              // uniform LDG.128
            const float bsel[4] = {bq.x, bq.y, bq.z, bq.w};

            #pragma unroll
            for (int u = 0; u < 4; u++) {                 // static select only
                const int f = f0 + g * 4 + u;
                const float* wf = c_w + f * 27 + 18;      // uniform LDC
                const float bv = bsel[u];
                u64 a0 = pack2(bv, bv);   // cols j, j+1
                u64 a1 = a0;              // cols j+2, j+3

                #pragma unroll
                for (int a = 0; a < 3; a++) {
                    #pragma unroll
                    for (int b = 0; b < 3; b++) {
                        const float ws = wf[a * 3 + b];   // constant port
                        const u64 wp = pack2(ws, ws);
                        a0 = ffma2(P[a][b],     wp, a0);
                        a1 = ffma2(P[a][b + 2], wp, a1);
                    }
                }

                // (1016*i + 4*j) % 16 == 0 by construction
                *reinterpret_cast<ulonglong2*>(ob) = make_ulonglong2(a0, a1);
                ob += (size_t)OIMG;
            }
        }
    } else {
        // ================= strip: ragged edges, one STG.128/filter =========
        // thread ip handles out[2ip][252..253] (right edge, even row) and
        // out[2ip+1][0..1] (left edge, odd row) -- contiguous 16B in memory.
        const int ip = tid;
        if (ip >= 127) return;
        const int i = ip * 2;

        // Right-edge inputs: rows i..i+2, cols 252..255 (float4 @ 1008B ok)
        // Left-edge inputs:  rows i+1..i+3, cols 0..3
        u64 PR[3][3], PL[3][3];
        #pragma unroll
        for (int r = 0; r < 3; r++) {
            const float4 a = *reinterpret_cast<const float4*>(
                xim + (size_t)(i + r) * Ww + 252);
            PR[r][0] = pack2(a.x, a.y);
            PR[r][1] = pack2(a.y, a.z);
            PR[r][2] = pack2(a.z, a.w);
            const float4 c = *reinterpret_cast<const float4*>(
                xim + (size_t)(i + 1 + r) * Ww);
            PL[r][0] = pack2(c.x, c.y);
            PL[r][1] = pack2(c.y, c.z);
            PL[r][2] = pack2(c.z, c.w);
        }

        // store base: out[i][252] .. out[i+1][1] = 4 consecutive floats,
        // byte offset 1016*i + 1008 ≡ 0 mod 16 (i even)
        float* ob = oimg + (size_t)i * WO + 252;

        #pragma unroll
        for (int g = 0; g < 4; g++) {
            const float4 bq = __ldg(b4 + g);
            const float bsel[4] = {bq.x, bq.y, bq.z, bq.w};

            #pragma unroll
            for (int u = 0; u < 4; u++) {
                const int f = f0 + g * 4 + u;
                const float* wf = c_w + f * 27 + 18;
                const float bv = bsel[u];
                u64 aR = pack2(bv, bv);   // out[i][252..253]
                u64 aL = aR;              // out[i+1][0..1]

                #pragma unroll
                for (int a = 0; a < 3; a++) {
                    #pragma unroll
                    for (int b = 0; b < 3; b++) {
                        const float ws = wf[a * 3 + b];
                        const u64 wp = pack2(ws, ws);
                        aR = ffma2(PR[a][b], wp, aR);
                        aL = ffma2(PL[a][b], wp, aL);
                    }
                }

                *reinterpret_cast<ulonglong2*>(ob) = make_ulonglong2(aR, aL);
                ob += (size_t)OIMG;
            }
        }
    }
}

extern "C" void kernel_launch(void* const* d_in, const int* in_sizes, int n_in,
                              void* d_out, int out_size) {
    const float* x    = (const float*)d_in[0];
    const float* w    = (const float*)d_in[1];
    const float* bias = (const float*)d_in[2];
    float* out        = (float*)d_out;

    // Single CE node: stage weights into constant memory (D2D, capturable).
    cudaMemcpyToSymbolAsync(c_w, w, F_OUT * 27 * sizeof(float), 0,
                            cudaMemcpyDeviceToDevice, 0);

    dim3 grid(128, NB, F_OUT / F_Q);   // (127 main + 1 strip, 16, 4)
    conv2dcq_kernel<<<grid, 128>>>(x, bias, out);
}